// round 3
// baseline (speedup 1.0000x reference)
#include <cuda_runtime.h>
#include <math.h>

#define SEQ   512
#define BATCH 64
#define IN    512
#define HID   1024

typedef unsigned long long ull;

// ---------------- device-global scratch (no runtime allocation) ------------
// x projections laid out [gate][t][col][b]  (b fastest)
__device__ float g_x[3u * SEQ * BATCH * HID];          // 402 MB
__device__ float g_hT[HID * BATCH];                    // h   [col][b]
__device__ float g_zT[HID * BATCH];                    // z   [col][b]
__device__ float g_rhT[HID * BATCH];                   // r*h [col][b]
__device__ unsigned int g_bar_count = 0;
__device__ volatile unsigned int g_bar_gen = 0;

// ---------------- packed f32x2 helpers -------------------------------------
__device__ __forceinline__ ull pack2(float lo, float hi) {
    ull r; asm("mov.b64 %0, {%1,%2};" : "=l"(r) : "f"(lo), "f"(hi)); return r;
}
__device__ __forceinline__ void unpack2(ull p, float& lo, float& hi) {
    asm("mov.b64 {%0,%1}, %2;" : "=f"(lo), "=f"(hi) : "l"(p));
}
__device__ __forceinline__ ull ffma2(ull a, ull b, ull c) {
    ull d; asm("fma.rn.f32x2 %0, %1, %2, %3;" : "=l"(d) : "l"(a), "l"(b), "l"(c));
    return d;
}
__device__ __forceinline__ float sigmoidf_(float x) {
    return 1.0f / (1.0f + __expf(-x));
}

// ---------------- grid barrier (monotonic generation, spin) ----------------
__device__ __forceinline__ void grid_sync(unsigned nblk, unsigned& gen) {
    __syncthreads();
    if (threadIdx.x == 0) {
        gen++;
        __threadfence();
        if (atomicAdd(&g_bar_count, 1u) == nblk - 1u) {
            *((volatile unsigned int*)&g_bar_count) = 0u;
            __threadfence();
            g_bar_gen = gen;
        } else {
            while (g_bar_gen < gen) { __nanosleep(32); }
        }
        __threadfence();
    }
    __syncthreads();
}

// ---------------- dynamic SMEM layout (floats) ------------------------------
#define OFF_WA   0         // 16384 f : A weights  [k][16]   (64 KB)
#define OFF_WB   16384     //  8192 f : B weights  [k][8]    (32 KB)
#define OFF_H    24576     // 16384 f : staging (A: 2x8192, B: 4x4096) (64 KB)
#define OFF_RED  40960     //   512 f : B half-reduction
#define SMEM_FLOATS 41472
#define SMEM_BYTES  (SMEM_FLOATS * 4)

// ===========================================================================
// Kernel 1: input projection -> X[gate][t][col][b]
// C[col][m] = sum_k W[k][col] * emb[m][k] + bias[col];  m = t*64 + b
// grid (8 col-tiles, 256 m-tiles, 3 gates), 256 threads, 128x128 tile, BK=16
// ===========================================================================
__global__ __launch_bounds__(256) void proj_kernel(
    const float* __restrict__ emb,
    const float* __restrict__ Wz, const float* __restrict__ Wr,
    const float* __restrict__ Wm,
    const float* __restrict__ bz, const float* __restrict__ br,
    const float* __restrict__ bm)
{
    const int gate = blockIdx.z;
    const float* W    = (gate == 0) ? Wz : (gate == 1) ? Wr : Wm;
    const float* bias = (gate == 0) ? bz : (gate == 1) ? br : bm;
    float* X = g_x + (size_t)gate * SEQ * BATCH * HID;

    const int Nb = blockIdx.x * 128;   // col tile
    const int Mb = blockIdx.y * 128;   // m tile (m = t*64+b)

    __shared__ float As[16][128];      // weights [k][col]
    __shared__ float Bs[16][132];      // emb^T   [k][m], padded

    const int tid = threadIdx.x;
    const int tx = tid & 15;           // m-lane
    const int ty = tid >> 4;           // col-lane

    ull acc[8][4];
    #pragma unroll
    for (int r = 0; r < 8; r++)
        #pragma unroll
        for (int p = 0; p < 4; p++) acc[r][p] = 0ull;

    for (int kb = 0; kb < IN; kb += 16) {
        #pragma unroll
        for (int i = 0; i < 2; i++) {
            int v = tid + i * 256;
            // A: 16 k x 128 cols, coalesced float4 along col
            int ak = v >> 5, acq = v & 31;
            *(float4*)&As[ak][acq * 4] =
                *(const float4*)&W[(size_t)(kb + ak) * HID + Nb + acq * 4];
            // B: emb rows, float4 along k, scatter-transpose
            int bm_ = v >> 2, bkq = v & 3;
            float4 e = *(const float4*)&emb[(size_t)(Mb + bm_) * IN + kb + bkq * 4];
            Bs[bkq * 4 + 0][bm_] = e.x;
            Bs[bkq * 4 + 1][bm_] = e.y;
            Bs[bkq * 4 + 2][bm_] = e.z;
            Bs[bkq * 4 + 3][bm_] = e.w;
        }
        __syncthreads();

        #pragma unroll
        for (int k = 0; k < 16; k++) {
            ulonglong2 b0 = *(const ulonglong2*)&Bs[k][tx * 8];
            ulonglong2 b1 = *(const ulonglong2*)&Bs[k][tx * 8 + 4];
            float4 w0 = *(const float4*)&As[k][ty * 8];
            float4 w1 = *(const float4*)&As[k][ty * 8 + 4];
            ull wd[8];
            wd[0] = pack2(w0.x, w0.x); wd[1] = pack2(w0.y, w0.y);
            wd[2] = pack2(w0.z, w0.z); wd[3] = pack2(w0.w, w0.w);
            wd[4] = pack2(w1.x, w1.x); wd[5] = pack2(w1.y, w1.y);
            wd[6] = pack2(w1.z, w1.z); wd[7] = pack2(w1.w, w1.w);
            #pragma unroll
            for (int r = 0; r < 8; r++) {
                acc[r][0] = ffma2(wd[r], b0.x, acc[r][0]);
                acc[r][1] = ffma2(wd[r], b0.y, acc[r][1]);
                acc[r][2] = ffma2(wd[r], b1.x, acc[r][2]);
                acc[r][3] = ffma2(wd[r], b1.y, acc[r][3]);
            }
        }
        __syncthreads();
    }

    // epilogue: thread's 8 m are consecutive -> same t, b0..b0+7
    const int m0 = Mb + tx * 8;
    const int t  = m0 >> 6;
    const int b0 = m0 & 63;
    #pragma unroll
    for (int r = 0; r < 8; r++) {
        int col = Nb + ty * 8 + r;
        float bsv = __ldg(&bias[col]);
        float m8[8];
        unpack2(acc[r][0], m8[0], m8[1]); unpack2(acc[r][1], m8[2], m8[3]);
        unpack2(acc[r][2], m8[4], m8[5]); unpack2(acc[r][3], m8[6], m8[7]);
        float* dst = &X[((size_t)t * HID + col) * BATCH + b0];
        *(float4*)dst =
            make_float4(m8[0] + bsv, m8[1] + bsv, m8[2] + bsv, m8[3] + bsv);
        *(float4*)(dst + 4) =
            make_float4(m8[4] + bsv, m8[5] + bsv, m8[6] + bsv, m8[7] + bsv);
    }
}

// ===========================================================================
// Kernel 2: init hT from init_h (transpose copy)
// ===========================================================================
__global__ void init_h_kernel(const float* __restrict__ ih) {
    int idx = blockIdx.x * blockDim.x + threadIdx.x;   // over HID*BATCH
    if (idx < HID * BATCH) {
        int col = idx >> 6, b = idx & 63;
        g_hT[idx] = ih[(size_t)b * HID + col];
    }
}

// ===========================================================================
// Kernel 3: persistent recurrence. 148 blocks x 256 threads, SMEM weights.
//  Blocks 0..63:  z cols blk*16..+16   | Wm cols blk*8..+8
//  Blocks 64..127: r cols (blk-64)*16  | Wm cols blk*8..+8
//  Blocks 128..147: barrier-only.
// ===========================================================================
__global__ __launch_bounds__(256, 1) void recur_kernel(
    const float* __restrict__ Wz, const float* __restrict__ Wr,
    const float* __restrict__ Wm, float* __restrict__ out)
{
    extern __shared__ float sm[];
    float* s_wA  = sm + OFF_WA;
    float* s_wB  = sm + OFF_WB;
    float* s_h   = sm + OFF_H;
    float* s_red = sm + OFF_RED;

    const int tid = threadIdx.x;
    const int blk = blockIdx.x;
    const bool work = (blk < 128);
    unsigned gen = 0;
    if (tid == 0) gen = g_bar_gen;     // resume monotonic count across launches

    // ---- one-time: cache weight column slices in SMEM ----
    if (work) {
        const int gate = blk >> 6;
        const int colbaseA = (blk & 63) * 16;
        const float* WA = (gate ? Wr : Wz) + (size_t)IN * HID;
        for (int v = tid; v < 16384; v += 256) {
            int k = v >> 4, c = v & 15;
            s_wA[v] = WA[(size_t)k * HID + colbaseA + c];
        }
        const int colbaseB = blk * 8;
        const float* WB = Wm + (size_t)IN * HID;
        for (int v = tid; v < 8192; v += 256) {
            int k = v >> 3, c = v & 7;
            s_wB[v] = WB[(size_t)k * HID + colbaseB + c];
        }
    }
    __syncthreads();

    const float* XZ = g_x;
    const float* XR = g_x + (size_t)SEQ * BATCH * HID;
    const float* XM = g_x + 2ull * SEQ * BATCH * HID;

    for (int t = 0; t < SEQ; t++) {
        // =================== stage A: z and r gates ========================
        if (work) {
            const int gate = blk >> 6;
            const int clA = tid & 15;
            const int bgA = (tid >> 4) & 7;

            float4 pf[8];
            #pragma unroll
            for (int i = 0; i < 8; i++)
                pf[i] = *(const float4*)&g_hT[(i * 256 + tid) * 4];

            ull acc0 = 0, acc1 = 0, acc2 = 0, acc3 = 0;

            for (int c = 0; c < 8; c++) {
                float* buf = s_h + (c & 1) * 8192;
                #pragma unroll
                for (int i = 0; i < 8; i++)
                    *(float4*)&buf[(i * 256 + tid) * 4] = pf[i];
                __syncthreads();
                if (c < 7) {
                    #pragma unroll
                    for (int i = 0; i < 8; i++)
                        pf[i] = *(const float4*)
                            &g_hT[(c + 1) * 8192 + (i * 256 + tid) * 4];
                }
                if (tid < 128) {
                    const float* wp = s_wA + c * 2048 + clA;
                    const float* hp = buf + bgA * 8;
                    #pragma unroll 8
                    for (int k = 0; k < 128; k++) {
                        float w = wp[k * 16];
                        ull w2 = pack2(w, w);
                        ulonglong2 hA = *(const ulonglong2*)(hp + k * 64);
                        ulonglong2 hB = *(const ulonglong2*)(hp + k * 64 + 4);
                        acc0 = ffma2(w2, hA.x, acc0);
                        acc1 = ffma2(w2, hA.y, acc1);
                        acc2 = ffma2(w2, hB.x, acc2);
                        acc3 = ffma2(w2, hB.y, acc3);
                    }
                }
                __syncthreads();
            }

            if (tid < 128) {
                const int col = (blk & 63) * 16 + clA;
                float a[8];
                unpack2(acc0, a[0], a[1]); unpack2(acc1, a[2], a[3]);
                unpack2(acc2, a[4], a[5]); unpack2(acc3, a[6], a[7]);
                const float* XG = gate ? XR : XZ;
                const float4* xg = (const float4*)
                    &XG[((size_t)t * HID + col) * BATCH + bgA * 8];
                float4 x0 = xg[0], x1 = xg[1];
                float xs[8] = {x0.x, x0.y, x0.z, x0.w, x1.x, x1.y, x1.z, x1.w};
                if (gate == 0) {
                    float zv[8];
                    #pragma unroll
                    for (int i = 0; i < 8; i++)
                        zv[i] = sigmoidf_(a[i] + xs[i]);
                    float* dz = &g_zT[col * BATCH + bgA * 8];
                    *(float4*)dz       = make_float4(zv[0], zv[1], zv[2], zv[3]);
                    *(float4*)(dz + 4) = make_float4(zv[4], zv[5], zv[6], zv[7]);
                } else {
                    const float4* hq = (const float4*)&g_hT[col * BATCH + bgA * 8];
                    float4 h0 = hq[0], h1 = hq[1];
                    float hv[8] = {h0.x, h0.y, h0.z, h0.w,
                                   h1.x, h1.y, h1.z, h1.w};
                    float rh[8];
                    #pragma unroll
                    for (int i = 0; i < 8; i++)
                        rh[i] = sigmoidf_(a[i] + xs[i]) * hv[i];
                    float* dr = &g_rhT[col * BATCH + bgA * 8];
                    *(float4*)dr       = make_float4(rh[0], rh[1], rh[2], rh[3]);
                    *(float4*)(dr + 4) = make_float4(rh[4], rh[5], rh[6], rh[7]);
                }
            }
        }
        grid_sync(gridDim.x, gen);

        // =================== stage B: candidate + update ===================
        if (work) {
            const int clB = tid & 7;
            const int bgB = (tid >> 3) & 7;
            const int half = tid >> 6;          // meaningful for tid<128

            float4 pf[8];
            #pragma unroll
            for (int i = 0; i < 8; i++) {
                int fidx = i * 256 + tid;
                int hh = fidx >> 10, off = fidx & 1023;
                pf[i] = *(const float4*)&g_rhT[hh * 32768 + off * 4];
            }

            ull acc0 = 0, acc1 = 0, acc2 = 0, acc3 = 0;

            for (int c = 0; c < 8; c++) {
                #pragma unroll
                for (int i = 0; i < 8; i++) {
                    int fidx = i * 256 + tid;
                    int hh = fidx >> 10, off = fidx & 1023;
                    *(float4*)&s_h[(hh * 2 + (c & 1)) * 4096 + off * 4] = pf[i];
                }
                __syncthreads();
                if (c < 7) {
                    #pragma unroll
                    for (int i = 0; i < 8; i++) {
                        int fidx = i * 256 + tid;
                        int hh = fidx >> 10, off = fidx & 1023;
                        pf[i] = *(const float4*)
                            &g_rhT[hh * 32768 + (c + 1) * 4096 + off * 4];
                    }
                }
                if (tid < 128) {
                    const float* wp = s_wB + (half * 512 + c * 64) * 8 + clB;
                    const float* hp = s_h + (half * 2 + (c & 1)) * 4096 + bgB * 8;
                    #pragma unroll 8
                    for (int k = 0; k < 64; k++) {
                        float w = wp[k * 8];
                        ull w2 = pack2(w, w);
                        ulonglong2 hA = *(const ulonglong2*)(hp + k * 64);
                        ulonglong2 hB = *(const ulonglong2*)(hp + k * 64 + 4);
                        acc0 = ffma2(w2, hA.x, acc0);
                        acc1 = ffma2(w2, hA.y, acc1);
                        acc2 = ffma2(w2, hB.x, acc2);
                        acc3 = ffma2(w2, hB.y, acc3);
                    }
                }
                __syncthreads();
            }

            // reduce the two K-halves
            if (tid >= 64 && tid < 128) {
                ull* rp = (ull*)s_red;
                rp[(tid - 64) * 4 + 0] = acc0;
                rp[(tid - 64) * 4 + 1] = acc1;
                rp[(tid - 64) * 4 + 2] = acc2;
                rp[(tid - 64) * 4 + 3] = acc3;
            }
            __syncthreads();
            if (tid < 64) {
                const ull* rp = (const ull*)s_red;
                float m8[8], o;
                float q0, q1;
                unpack2(acc0, m8[0], m8[1]); unpack2(acc1, m8[2], m8[3]);
                unpack2(acc2, m8[4], m8[5]); unpack2(acc3, m8[6], m8[7]);
                #pragma unroll
                for (int i = 0; i < 4; i++) {
                    unpack2(rp[tid * 4 + i], q0, q1);
                    m8[2 * i] += q0; m8[2 * i + 1] += q1; (void)o;
                }
                const int col = blk * 8 + clB;
                const float4* xm = (const float4*)
                    &XM[((size_t)t * HID + col) * BATCH + bgB * 8];
                float4 x0 = xm[0], x1 = xm[1];
                float xs[8] = {x0.x, x0.y, x0.z, x0.w, x1.x, x1.y, x1.z, x1.w};
                const float4* zq = (const float4*)&g_zT[col * BATCH + bgB * 8];
                float4 z0 = zq[0], z1 = zq[1];
                float zs[8] = {z0.x, z0.y, z0.z, z0.w, z1.x, z1.y, z1.z, z1.w};
                const float4* hq = (const float4*)&g_hT[col * BATCH + bgB * 8];
                float4 h0 = hq[0], h1 = hq[1];
                float hs[8] = {h0.x, h0.y, h0.z, h0.w, h1.x, h1.y, h1.z, h1.w};
                float hn[8];
                #pragma unroll
                for (int i = 0; i < 8; i++) {
                    float ht = tanhf(m8[i] + xs[i]);
                    hn[i] = (1.0f - zs[i]) * hs[i] + zs[i] * ht;
                }
                float* dh = &g_hT[col * BATCH + bgB * 8];
                *(float4*)dh       = make_float4(hn[0], hn[1], hn[2], hn[3]);
                *(float4*)(dh + 4) = make_float4(hn[4], hn[5], hn[6], hn[7]);
                #pragma unroll
                for (int j = 0; j < 8; j++) {
                    int b = bgB * 8 + j;
                    out[(size_t)b * SEQ * HID + (size_t)t * HID + col] = hn[j];
                }
            }
        }
        grid_sync(gridDim.x, gen);
    }
}

// ===========================================================================
extern "C" void kernel_launch(void* const* d_in, const int* in_sizes, int n_in,
                              void* d_out, int out_size)
{
    const float* emb = (const float*)d_in[0];
    const float* ih  = (const float*)d_in[1];
    const float* Wz  = (const float*)d_in[2];
    const float* bz  = (const float*)d_in[3];
    const float* Wr  = (const float*)d_in[4];
    const float* br  = (const float*)d_in[5];
    const float* Wm  = (const float*)d_in[6];
    const float* bm  = (const float*)d_in[7];
    float* out = (float*)d_out;

    cudaFuncSetAttribute(recur_kernel,
                         cudaFuncAttributeMaxDynamicSharedMemorySize, SMEM_BYTES);

    proj_kernel<<<dim3(HID / 128, (SEQ * BATCH) / 128, 3), 256>>>(
        emb, Wz, Wr, Wm, bz, br, bm);
    init_h_kernel<<<(HID * BATCH + 255) / 256, 256>>>(ih);
    recur_kernel<<<148, 256, SMEM_BYTES>>>(Wz, Wr, Wm, out);
}

// round 8
// speedup vs baseline: 1.0693x; 1.0693x over previous
#include <cuda_runtime.h>
#include <math.h>

#define SEQ   512
#define BATCH 64
#define IN    512
#define HID   1024
#define NCTA  128

typedef unsigned long long ull;

// ---------------- device-global scratch (no runtime allocation) ------------
// x projections laid out [gate][t][col][b]  (b fastest)
__device__ float g_x[3u * SEQ * BATCH * HID];
__device__ float g_hT[HID * BATCH];                    // h   [col][b]
__device__ float g_zT[HID * BATCH];                    // z   [col][b]
__device__ float g_rhT[HID * BATCH];                   // r*h [col][b]
// barrier state: per-CTA arrival flags (128B apart) + release word
__device__ volatile unsigned g_arrive[NCTA * 32];
__device__ volatile unsigned g_release;

// ---------------- packed f32x2 helpers -------------------------------------
__device__ __forceinline__ ull pack2(float lo, float hi) {
    ull r; asm("mov.b64 %0, {%1,%2};" : "=l"(r) : "f"(lo), "f"(hi)); return r;
}
__device__ __forceinline__ void unpack2(ull p, float& lo, float& hi) {
    asm("mov.b64 {%0,%1}, %2;" : "=f"(lo), "=f"(hi) : "l"(p));
}
__device__ __forceinline__ ull ffma2(ull a, ull b, ull c) {
    ull d; asm("fma.rn.f32x2 %0, %1, %2, %3;" : "=l"(d) : "l"(a), "l"(b), "l"(c));
    return d;
}
__device__ __forceinline__ float sigmoidf_(float x) {
    return 1.0f / (1.0f + __expf(-x));
}

// ---------------- grid barrier: flags + gather + release, no atomics -------
__device__ __forceinline__ void grid_barrier(unsigned& gen) {
    gen++;
    __syncthreads();
    if (threadIdx.x == 0) {
        __threadfence();
        g_arrive[blockIdx.x * 32] = gen;
    }
    if (blockIdx.x == 0) {
        if (threadIdx.x < NCTA) {
            while (g_arrive[threadIdx.x * 32] < gen) { }
        }
        __syncthreads();
        if (threadIdx.x == 0) {
            __threadfence();
            g_release = gen;
        }
    }
    if (threadIdx.x == 0) {
        while (g_release < gen) { }
        __threadfence();
    }
    __syncthreads();
}

// ---------------- dynamic SMEM layout (float offsets) ----------------------
// chunk = 128 k-rows x 64 batches = 8192 floats (32 KB); double buffered.
#define OFF_WA   0         // 16384 f : A weights [k][16]   (64 KB)
#define OFF_WB   16384     //  8192 f : B weights [k][8]    (32 KB)
#define OFF_H    24576     // 16384 f : 2 x chunk buffers   (64 KB)
#define OFF_RED  40960     //  2048 f : split-K reduction    (8 KB)
#define SMEM_FLOATS 43008
#define SMEM_BYTES  (SMEM_FLOATS * 4)   // 168 KB

// ===========================================================================
// Kernel 1: input projection -> X[gate][t][col][b]
// ===========================================================================
__global__ __launch_bounds__(256) void proj_kernel(
    const float* __restrict__ emb,
    const float* __restrict__ Wz, const float* __restrict__ Wr,
    const float* __restrict__ Wm,
    const float* __restrict__ bz, const float* __restrict__ br,
    const float* __restrict__ bm)
{
    const int gate = blockIdx.z;
    const float* W    = (gate == 0) ? Wz : (gate == 1) ? Wr : Wm;
    const float* bias = (gate == 0) ? bz : (gate == 1) ? br : bm;
    float* X = g_x + (size_t)gate * SEQ * BATCH * HID;

    const int Nb = blockIdx.x * 128;   // col tile
    const int Mb = blockIdx.y * 128;   // m tile (m = t*64+b)

    __shared__ float As[16][128];      // weights [k][col]
    __shared__ float Bs[16][132];      // emb^T   [k][m], padded

    const int tid = threadIdx.x;
    const int tx = tid & 15;           // m-lane
    const int ty = tid >> 4;           // col-lane

    ull acc[8][4];
    #pragma unroll
    for (int r = 0; r < 8; r++)
        #pragma unroll
        for (int p = 0; p < 4; p++) acc[r][p] = 0ull;

    for (int kb = 0; kb < IN; kb += 16) {
        #pragma unroll
        for (int i = 0; i < 2; i++) {
            int v = tid + i * 256;
            int ak = v >> 5, acq = v & 31;
            *(float4*)&As[ak][acq * 4] =
                *(const float4*)&W[(size_t)(kb + ak) * HID + Nb + acq * 4];
            int bm_ = v >> 2, bkq = v & 3;
            float4 e = *(const float4*)&emb[(size_t)(Mb + bm_) * IN + kb + bkq * 4];
            Bs[bkq * 4 + 0][bm_] = e.x;
            Bs[bkq * 4 + 1][bm_] = e.y;
            Bs[bkq * 4 + 2][bm_] = e.z;
            Bs[bkq * 4 + 3][bm_] = e.w;
        }
        __syncthreads();

        #pragma unroll
        for (int k = 0; k < 16; k++) {
            ulonglong2 b0 = *(const ulonglong2*)&Bs[k][tx * 8];
            ulonglong2 b1 = *(const ulonglong2*)&Bs[k][tx * 8 + 4];
            float4 w0 = *(const float4*)&As[k][ty * 8];
            float4 w1 = *(const float4*)&As[k][ty * 8 + 4];
            ull wd[8];
            wd[0] = pack2(w0.x, w0.x); wd[1] = pack2(w0.y, w0.y);
            wd[2] = pack2(w0.z, w0.z); wd[3] = pack2(w0.w, w0.w);
            wd[4] = pack2(w1.x, w1.x); wd[5] = pack2(w1.y, w1.y);
            wd[6] = pack2(w1.z, w1.z); wd[7] = pack2(w1.w, w1.w);
            #pragma unroll
            for (int r = 0; r < 8; r++) {
                acc[r][0] = ffma2(wd[r], b0.x, acc[r][0]);
                acc[r][1] = ffma2(wd[r], b0.y, acc[r][1]);
                acc[r][2] = ffma2(wd[r], b1.x, acc[r][2]);
                acc[r][3] = ffma2(wd[r], b1.y, acc[r][3]);
            }
        }
        __syncthreads();
    }

    const int m0 = Mb + tx * 8;
    const int t  = m0 >> 6;
    const int b0 = m0 & 63;
    #pragma unroll
    for (int r = 0; r < 8; r++) {
        int col = Nb + ty * 8 + r;
        float bsv = __ldg(&bias[col]);
        float m8[8];
        unpack2(acc[r][0], m8[0], m8[1]); unpack2(acc[r][1], m8[2], m8[3]);
        unpack2(acc[r][2], m8[4], m8[5]); unpack2(acc[r][3], m8[6], m8[7]);
        float* dst = &X[((size_t)t * HID + col) * BATCH + b0];
        *(float4*)dst =
            make_float4(m8[0] + bsv, m8[1] + bsv, m8[2] + bsv, m8[3] + bsv);
        *(float4*)(dst + 4) =
            make_float4(m8[4] + bsv, m8[5] + bsv, m8[6] + bsv, m8[7] + bsv);
    }
}

// ===========================================================================
// Kernel 2: init hT from init_h (transpose copy)
// ===========================================================================
__global__ void init_h_kernel(const float* __restrict__ ih) {
    int idx = blockIdx.x * blockDim.x + threadIdx.x;
    if (idx < HID * BATCH) {
        int col = idx >> 6, b = idx & 63;
        g_hT[idx] = ih[(size_t)b * HID + col];
    }
}

// ===========================================================================
// Kernel 3: persistent recurrence. 128 CTAs x 256 threads.
//  Blocks 0..63:  z cols blk*16..+16   | Wm cols blk*8..+8
//  Blocks 64..127: r cols (blk-64)*16  | Wm cols blk*8..+8
// h/rh staged in 8 chunks of 128k x 64b, double buffered.
// Stage A: thread = (16 col, 8 bgrp, 2 Khalf-within-chunk);  B: (8, 8, 4).
// ===========================================================================
__global__ __launch_bounds__(256, 1) void recur_kernel(
    const float* __restrict__ Wz, const float* __restrict__ Wr,
    const float* __restrict__ Wm, float* __restrict__ out)
{
    extern __shared__ float sm[];
    float* s_wA = sm + OFF_WA;
    float* s_wB = sm + OFF_WB;
    float* s_h  = sm + OFF_H;
    ull*   s_red = (ull*)(sm + OFF_RED);

    const int tid = threadIdx.x;
    const int blk = blockIdx.x;
    const int gate = blk >> 6;

    unsigned gen = g_release;          // monotonic across graph replays

    // ---- one-time: cache weight column slices in SMEM ----
    {
        const int colbaseA = (blk & 63) * 16;
        const float* WA = (gate ? Wr : Wz) + (size_t)IN * HID;
        for (int v = tid; v < 16384; v += 256) {
            int k = v >> 4, c = v & 15;
            s_wA[v] = WA[(size_t)k * HID + colbaseA + c];
        }
        const int colbaseB = blk * 8;
        const float* WB = Wm + (size_t)IN * HID;
        for (int v = tid; v < 8192; v += 256) {
            int k = v >> 3, c = v & 7;
            s_wB[v] = WB[(size_t)k * HID + colbaseB + c];
        }
    }
    __syncthreads();

    const float* XZ = g_x;
    const float* XR = g_x + (size_t)SEQ * BATCH * HID;
    const float* XM = g_x + 2ull * SEQ * BATCH * HID;

    const int clA = tid & 15;          // stage A col lane
    const int bgA = (tid >> 4) & 7;    // batch group (8 b's)
    const int khA = tid >> 7;          // K half within chunk (64 k)
    const int clB = tid & 7;           // stage B col lane
    const int bgB = (tid >> 3) & 7;
    const int khB = tid >> 6;          // K quarter within chunk (32 k)

    for (int t = 0; t < SEQ; t++) {
        // =================== stage A: z / r gate ===========================
        {
            ull acc0 = 0, acc1 = 0, acc2 = 0, acc3 = 0;
            float4 pf[8];
            #pragma unroll
            for (int i = 0; i < 8; i++)
                pf[i] = *(const float4*)&g_hT[(i * 256 + tid) * 4];

            for (int c = 0; c < 8; c++) {
                float* buf = s_h + (c & 1) * 8192;
                #pragma unroll
                for (int i = 0; i < 8; i++)
                    *(float4*)&buf[(i * 256 + tid) * 4] = pf[i];
                __syncthreads();
                if (c < 7) {
                    #pragma unroll
                    for (int i = 0; i < 8; i++)
                        pf[i] = *(const float4*)
                            &g_hT[(c + 1) * 8192 + (i * 256 + tid) * 4];
                }
                const float* wp = s_wA + (c * 128 + khA * 64) * 16 + clA;
                const float* hp = buf + khA * 4096 + bgA * 8;
                #pragma unroll 8
                for (int k = 0; k < 64; k++) {
                    float w = wp[k * 16];
                    ull w2 = pack2(w, w);
                    ulonglong2 hA = *(const ulonglong2*)(hp + k * 64);
                    ulonglong2 hB = *(const ulonglong2*)(hp + k * 64 + 4);
                    acc0 = ffma2(w2, hA.x, acc0);
                    acc1 = ffma2(w2, hA.y, acc1);
                    acc2 = ffma2(w2, hB.x, acc2);
                    acc3 = ffma2(w2, hB.y, acc3);
                }
            }

            if (khA == 1) {
                ull* rp = s_red + (tid & 127) * 4;
                rp[0] = acc0; rp[1] = acc1; rp[2] = acc2; rp[3] = acc3;
            }
            __syncthreads();
            if (khA == 0) {
                const ull* rp = s_red + tid * 4;
                float a[8], q0, q1;
                unpack2(acc0, a[0], a[1]); unpack2(acc1, a[2], a[3]);
                unpack2(acc2, a[4], a[5]); unpack2(acc3, a[6], a[7]);
                #pragma unroll
                for (int i = 0; i < 4; i++) {
                    unpack2(rp[i], q0, q1);
                    a[2 * i] += q0; a[2 * i + 1] += q1;
                }
                const int col = (blk & 63) * 16 + clA;
                const float* XG = gate ? XR : XZ;
                const float4* xg = (const float4*)
                    &XG[((size_t)t * HID + col) * BATCH + bgA * 8];
                float4 x0 = xg[0], x1 = xg[1];
                float xs[8] = {x0.x, x0.y, x0.z, x0.w, x1.x, x1.y, x1.z, x1.w};
                if (gate == 0) {
                    float zv[8];
                    #pragma unroll
                    for (int i = 0; i < 8; i++)
                        zv[i] = sigmoidf_(a[i] + xs[i]);
                    float* dz = &g_zT[col * BATCH + bgA * 8];
                    *(float4*)dz       = make_float4(zv[0], zv[1], zv[2], zv[3]);
                    *(float4*)(dz + 4) = make_float4(zv[4], zv[5], zv[6], zv[7]);
                } else {
                    const float4* hq = (const float4*)&g_hT[col * BATCH + bgA * 8];
                    float4 h0 = hq[0], h1 = hq[1];
                    float hv[8] = {h0.x, h0.y, h0.z, h0.w,
                                   h1.x, h1.y, h1.z, h1.w};
                    float rh[8];
                    #pragma unroll
                    for (int i = 0; i < 8; i++)
                        rh[i] = sigmoidf_(a[i] + xs[i]) * hv[i];
                    float* dr = &g_rhT[col * BATCH + bgA * 8];
                    *(float4*)dr       = make_float4(rh[0], rh[1], rh[2], rh[3]);
                    *(float4*)(dr + 4) = make_float4(rh[4], rh[5], rh[6], rh[7]);
                }
            }
        }
        grid_barrier(gen);

        // =================== stage B: candidate + update ===================
        {
            ull acc0 = 0, acc1 = 0, acc2 = 0, acc3 = 0;
            float4 pf[8];
            #pragma unroll
            for (int i = 0; i < 8; i++)
                pf[i] = *(const float4*)&g_rhT[(i * 256 + tid) * 4];

            for (int c = 0; c < 8; c++) {
                float* buf = s_h + (c & 1) * 8192;
                #pragma unroll
                for (int i = 0; i < 8; i++)
                    *(float4*)&buf[(i * 256 + tid) * 4] = pf[i];
                __syncthreads();
                if (c < 7) {
                    #pragma unroll
                    for (int i = 0; i < 8; i++)
                        pf[i] = *(const float4*)
                            &g_rhT[(c + 1) * 8192 + (i * 256 + tid) * 4];
                }
                const float* wp = s_wB + (c * 128 + khB * 32) * 8 + clB;
                const float* hp = buf + khB * 2048 + bgB * 8;
                #pragma unroll 8
                for (int k = 0; k < 32; k++) {
                    float w = wp[k * 8];
                    ull w2 = pack2(w, w);
                    ulonglong2 hA = *(const ulonglong2*)(hp + k * 64);
                    ulonglong2 hB = *(const ulonglong2*)(hp + k * 64 + 4);
                    acc0 = ffma2(w2, hA.x, acc0);
                    acc1 = ffma2(w2, hA.y, acc1);
                    acc2 = ffma2(w2, hB.x, acc2);
                    acc3 = ffma2(w2, hB.y, acc3);
                }
            }

            if (khB > 0) {
                ull* rp = s_red + ((khB - 1) * 64 + (tid & 63)) * 4;
                rp[0] = acc0; rp[1] = acc1; rp[2] = acc2; rp[3] = acc3;
            }
            __syncthreads();
            if (khB == 0) {
                float m8[8], q0, q1;
                unpack2(acc0, m8[0], m8[1]); unpack2(acc1, m8[2], m8[3]);
                unpack2(acc2, m8[4], m8[5]); unpack2(acc3, m8[6], m8[7]);
                #pragma unroll
                for (int j = 0; j < 3; j++) {
                    const ull* rp = s_red + (j * 64 + tid) * 4;
                    #pragma unroll
                    for (int i = 0; i < 4; i++) {
                        unpack2(rp[i], q0, q1);
                        m8[2 * i] += q0; m8[2 * i + 1] += q1;
                    }
                }
                const int col = blk * 8 + clB;
                const float4* xm = (const float4*)
                    &XM[((size_t)t * HID + col) * BATCH + bgB * 8];
                float4 x0 = xm[0], x1 = xm[1];
                float xs[8] = {x0.x, x0.y, x0.z, x0.w, x1.x, x1.y, x1.z, x1.w};
                const float4* zq = (const float4*)&g_zT[col * BATCH + bgB * 8];
                float4 z0 = zq[0], z1 = zq[1];
                float zs[8] = {z0.x, z0.y, z0.z, z0.w, z1.x, z1.y, z1.z, z1.w};
                const float4* hq = (const float4*)&g_hT[col * BATCH + bgB * 8];
                float4 h0 = hq[0], h1 = hq[1];
                float hs[8] = {h0.x, h0.y, h0.z, h0.w, h1.x, h1.y, h1.z, h1.w};
                float hn[8];
                #pragma unroll
                for (int i = 0; i < 8; i++) {
                    float ht = tanhf(m8[i] + xs[i]);
                    hn[i] = (1.0f - zs[i]) * hs[i] + zs[i] * ht;
                }
                float* dh = &g_hT[col * BATCH + bgB * 8];
                *(float4*)dh       = make_float4(hn[0], hn[1], hn[2], hn[3]);
                *(float4*)(dh + 4) = make_float4(hn[4], hn[5], hn[6], hn[7]);
                #pragma unroll
                for (int j = 0; j < 8; j++) {
                    int b = bgB * 8 + j;
                    out[((size_t)b * SEQ + t) * HID + col] = hn[j];
                }
            }
        }
        grid_barrier(gen);
    }
}

// ===========================================================================
extern "C" void kernel_launch(void* const* d_in, const int* in_sizes, int n_in,
                              void* d_out, int out_size)
{
    const float* emb = (const float*)d_in[0];
    const float* ih  = (const float*)d_in[1];
    const float* Wz  = (const float*)d_in[2];
    const float* bz  = (const float*)d_in[3];
    const float* Wr  = (const float*)d_in[4];
    const float* br  = (const float*)d_in[5];
    const float* Wm  = (const float*)d_in[6];
    const float* bm  = (const float*)d_in[7];
    float* out = (float*)d_out;

    cudaFuncSetAttribute(recur_kernel,
                         cudaFuncAttributeMaxDynamicSharedMemorySize, SMEM_BYTES);

    proj_kernel<<<dim3(HID / 128, (SEQ * BATCH) / 128, 3), 256>>>(
        emb, Wz, Wr, Wm, bz, br, bm);
    init_h_kernel<<<(HID * BATCH + 255) / 256, 256>>>(ih);
    recur_kernel<<<NCTA, 256, SMEM_BYTES>>>(Wz, Wr, Wm, out);
}

// round 13
// speedup vs baseline: 1.1061x; 1.0344x over previous
#include <cuda_runtime.h>
#include <math.h>

#define SEQ   512
#define BATCH 64
#define IN    512
#define HID   1024
#define NCTA  128
#define NTHR  512

typedef unsigned long long ull;

// ---------------- device-global scratch (no runtime allocation) ------------
// x projections laid out [gate][t][col][b]  (b fastest)
__device__ float g_x[3u * SEQ * BATCH * HID];
__device__ float g_hT[HID * BATCH];                    // h   [col][b]
__device__ float g_zT[HID * BATCH];                    // z   [col][b]
__device__ float g_rhT[HID * BATCH];                   // r*h [col][b]
// barrier state: per-CTA arrival flags (128B apart) + release word
__device__ volatile unsigned g_arrive[NCTA * 32];
__device__ volatile unsigned g_release;

// ---------------- packed f32x2 helpers -------------------------------------
__device__ __forceinline__ ull pack2(float lo, float hi) {
    ull r; asm("mov.b64 %0, {%1,%2};" : "=l"(r) : "f"(lo), "f"(hi)); return r;
}
__device__ __forceinline__ void unpack2(ull p, float& lo, float& hi) {
    asm("mov.b64 {%0,%1}, %2;" : "=f"(lo), "=f"(hi) : "l"(p));
}
__device__ __forceinline__ ull ffma2(ull a, ull b, ull c) {
    ull d; asm("fma.rn.f32x2 %0, %1, %2, %3;" : "=l"(d) : "l"(a), "l"(b), "l"(c));
    return d;
}
__device__ __forceinline__ float sigmoidf_(float x) {
    return 1.0f / (1.0f + __expf(-x));
}

// ---------------- grid barrier: flags + gather + release, no atomics -------
__device__ __forceinline__ void grid_barrier(unsigned& gen) {
    gen++;
    __syncthreads();
    if (threadIdx.x == 0) {
        __threadfence();
        g_arrive[blockIdx.x * 32] = gen;
    }
    if (blockIdx.x == 0) {
        if (threadIdx.x < NCTA) {
            while (g_arrive[threadIdx.x * 32] < gen) { }
        }
        __syncthreads();
        if (threadIdx.x == 0) {
            __threadfence();
            g_release = gen;
        }
    }
    if (threadIdx.x == 0) {
        while (g_release < gen) { }
        __threadfence();
    }
    __syncthreads();
}

// ---------------- dynamic SMEM layout (float offsets) ----------------------
// chunk = 128 k-rows x 64 batches = 8192 floats (32 KB); double buffered.
#define OFF_WA   0         // 16384 f : A weights [k][16]   (64 KB)
#define OFF_WB   16384     //  8192 f : B weights [k][8]    (32 KB)
#define OFF_H    24576     // 16384 f : 2 x chunk buffers   (64 KB)
#define OFF_RED  40960     //  3584 f : split-K reduction   (14 KB)
#define SMEM_FLOATS 44544
#define SMEM_BYTES  (SMEM_FLOATS * 4)   // 174 KB

// ===========================================================================
// Kernel 1: input projection -> X[gate][t][col][b]   (measured at FMA floor)
// ===========================================================================
__global__ __launch_bounds__(256) void proj_kernel(
    const float* __restrict__ emb,
    const float* __restrict__ Wz, const float* __restrict__ Wr,
    const float* __restrict__ Wm,
    const float* __restrict__ bz, const float* __restrict__ br,
    const float* __restrict__ bm)
{
    const int gate = blockIdx.z;
    const float* W    = (gate == 0) ? Wz : (gate == 1) ? Wr : Wm;
    const float* bias = (gate == 0) ? bz : (gate == 1) ? br : bm;
    float* X = g_x + (size_t)gate * SEQ * BATCH * HID;

    const int Nb = blockIdx.x * 128;   // col tile
    const int Mb = blockIdx.y * 128;   // m tile (m = t*64+b)

    __shared__ float As[16][128];      // weights [k][col]
    __shared__ float Bs[16][132];      // emb^T   [k][m], padded

    const int tid = threadIdx.x;
    const int tx = tid & 15;           // m-lane
    const int ty = tid >> 4;           // col-lane

    ull acc[8][4];
    #pragma unroll
    for (int r = 0; r < 8; r++)
        #pragma unroll
        for (int p = 0; p < 4; p++) acc[r][p] = 0ull;

    for (int kb = 0; kb < IN; kb += 16) {
        #pragma unroll
        for (int i = 0; i < 2; i++) {
            int v = tid + i * 256;
            int ak = v >> 5, acq = v & 31;
            *(float4*)&As[ak][acq * 4] =
                *(const float4*)&W[(size_t)(kb + ak) * HID + Nb + acq * 4];
            int bm_ = v >> 2, bkq = v & 3;
            float4 e = *(const float4*)&emb[(size_t)(Mb + bm_) * IN + kb + bkq * 4];
            Bs[bkq * 4 + 0][bm_] = e.x;
            Bs[bkq * 4 + 1][bm_] = e.y;
            Bs[bkq * 4 + 2][bm_] = e.z;
            Bs[bkq * 4 + 3][bm_] = e.w;
        }
        __syncthreads();

        #pragma unroll
        for (int k = 0; k < 16; k++) {
            ulonglong2 b0 = *(const ulonglong2*)&Bs[k][tx * 8];
            ulonglong2 b1 = *(const ulonglong2*)&Bs[k][tx * 8 + 4];
            float4 w0 = *(const float4*)&As[k][ty * 8];
            float4 w1 = *(const float4*)&As[k][ty * 8 + 4];
            ull wd[8];
            wd[0] = pack2(w0.x, w0.x); wd[1] = pack2(w0.y, w0.y);
            wd[2] = pack2(w0.z, w0.z); wd[3] = pack2(w0.w, w0.w);
            wd[4] = pack2(w1.x, w1.x); wd[5] = pack2(w1.y, w1.y);
            wd[6] = pack2(w1.z, w1.z); wd[7] = pack2(w1.w, w1.w);
            #pragma unroll
            for (int r = 0; r < 8; r++) {
                acc[r][0] = ffma2(wd[r], b0.x, acc[r][0]);
                acc[r][1] = ffma2(wd[r], b0.y, acc[r][1]);
                acc[r][2] = ffma2(wd[r], b1.x, acc[r][2]);
                acc[r][3] = ffma2(wd[r], b1.y, acc[r][3]);
            }
        }
        __syncthreads();
    }

    const int m0 = Mb + tx * 8;
    const int t  = m0 >> 6;
    const int b0 = m0 & 63;
    #pragma unroll
    for (int r = 0; r < 8; r++) {
        int col = Nb + ty * 8 + r;
        float bsv = __ldg(&bias[col]);
        float m8[8];
        unpack2(acc[r][0], m8[0], m8[1]); unpack2(acc[r][1], m8[2], m8[3]);
        unpack2(acc[r][2], m8[4], m8[5]); unpack2(acc[r][3], m8[6], m8[7]);
        float* dst = &X[((size_t)t * HID + col) * BATCH + b0];
        *(float4*)dst =
            make_float4(m8[0] + bsv, m8[1] + bsv, m8[2] + bsv, m8[3] + bsv);
        *(float4*)(dst + 4) =
            make_float4(m8[4] + bsv, m8[5] + bsv, m8[6] + bsv, m8[7] + bsv);
    }
}

// ===========================================================================
// Kernel 2: init hT from init_h (transpose copy)
// ===========================================================================
__global__ void init_h_kernel(const float* __restrict__ ih) {
    int idx = blockIdx.x * blockDim.x + threadIdx.x;
    if (idx < HID * BATCH) {
        int col = idx >> 6, b = idx & 63;
        g_hT[idx] = ih[(size_t)b * HID + col];
    }
}

// ===========================================================================
// Kernel 3: persistent recurrence. 128 CTAs x 512 threads (4 warps/SMSP).
//  Blocks 0..63:  z cols blk*16..+16   | Wm cols blk*8..+8
//  Blocks 64..127: r cols (blk-64)*16  | Wm cols blk*8..+8
// h/rh staged in 8 chunks of 128k x 64b, double buffered.
// Stage A: thread = (16 col, 8 bgrp, 4 ks of 32k/chunk); B: (8, 8, 8 ks of 16k).
// ===========================================================================
__global__ __launch_bounds__(NTHR, 1) void recur_kernel(
    const float* __restrict__ Wz, const float* __restrict__ Wr,
    const float* __restrict__ Wm, float* __restrict__ out)
{
    extern __shared__ float sm[];
    float* s_wA = sm + OFF_WA;
    float* s_wB = sm + OFF_WB;
    float* s_h  = sm + OFF_H;
    ull*   s_red = (ull*)(sm + OFF_RED);

    const int tid = threadIdx.x;
    const int blk = blockIdx.x;
    const int gate = blk >> 6;

    unsigned gen = g_release;          // monotonic across graph replays

    // ---- one-time: cache weight column slices in SMEM ----
    {
        const int colbaseA = (blk & 63) * 16;
        const float* WA = (gate ? Wr : Wz) + (size_t)IN * HID;
        for (int v = tid; v < 16384; v += NTHR) {
            int k = v >> 4, c = v & 15;
            s_wA[v] = WA[(size_t)k * HID + colbaseA + c];
        }
        const int colbaseB = blk * 8;
        const float* WB = Wm + (size_t)IN * HID;
        for (int v = tid; v < 8192; v += NTHR) {
            int k = v >> 3, c = v & 7;
            s_wB[v] = WB[(size_t)k * HID + colbaseB + c];
        }
    }
    __syncthreads();

    const float* XZ = g_x;
    const float* XR = g_x + (size_t)SEQ * BATCH * HID;
    const float* XM = g_x + 2ull * SEQ * BATCH * HID;

    const int clA = tid & 15;          // stage A col lane
    const int bgA = (tid >> 4) & 7;    // batch group (8 b's)
    const int ksA = tid >> 7;          // K split 0..3 (32 k per chunk)
    const int clB = tid & 7;           // stage B col lane
    const int bgB = (tid >> 3) & 7;
    const int ksB = tid >> 6;          // K split 0..7 (16 k per chunk)

    for (int t = 0; t < SEQ; t++) {
        // =================== stage A: z / r gate ===========================
        {
            // hoist x-gate loads (cold DRAM) so latency overlaps the K loop
            float4 xg0, xg1;
            const int colE = (blk & 63) * 16 + clA;
            if (ksA == 0) {
                const float* XG = gate ? XR : XZ;
                const float4* xg = (const float4*)
                    &XG[((size_t)t * HID + colE) * BATCH + bgA * 8];
                xg0 = xg[0]; xg1 = xg[1];
            }

            ull acc0 = 0, acc1 = 0, acc2 = 0, acc3 = 0;
            float4 pf[4];
            #pragma unroll
            for (int i = 0; i < 4; i++)
                pf[i] = *(const float4*)&g_hT[(i * NTHR + tid) * 4];

            for (int c = 0; c < 8; c++) {
                float* buf = s_h + (c & 1) * 8192;
                #pragma unroll
                for (int i = 0; i < 4; i++)
                    *(float4*)&buf[(i * NTHR + tid) * 4] = pf[i];
                __syncthreads();
                if (c < 7) {
                    #pragma unroll
                    for (int i = 0; i < 4; i++)
                        pf[i] = *(const float4*)
                            &g_hT[(c + 1) * 8192 + (i * NTHR + tid) * 4];
                }
                const float* wp = s_wA + (c * 128 + ksA * 32) * 16 + clA;
                const float* hp = buf + ksA * 32 * 64 + bgA * 8;
                #pragma unroll 8
                for (int k = 0; k < 32; k++) {
                    float w = wp[k * 16];
                    ull w2 = pack2(w, w);
                    ulonglong2 hA = *(const ulonglong2*)(hp + k * 64);
                    ulonglong2 hB = *(const ulonglong2*)(hp + k * 64 + 4);
                    acc0 = ffma2(w2, hA.x, acc0);
                    acc1 = ffma2(w2, hA.y, acc1);
                    acc2 = ffma2(w2, hB.x, acc2);
                    acc3 = ffma2(w2, hB.y, acc3);
                }
            }

            if (ksA > 0) {
                ull* rp = s_red + ((ksA - 1) * 128 + (tid & 127)) * 4;
                rp[0] = acc0; rp[1] = acc1; rp[2] = acc2; rp[3] = acc3;
            }
            __syncthreads();
            if (ksA == 0) {
                float a[8], q0, q1;
                unpack2(acc0, a[0], a[1]); unpack2(acc1, a[2], a[3]);
                unpack2(acc2, a[4], a[5]); unpack2(acc3, a[6], a[7]);
                #pragma unroll
                for (int j = 0; j < 3; j++) {
                    const ull* rp = s_red + (j * 128 + tid) * 4;
                    #pragma unroll
                    for (int i = 0; i < 4; i++) {
                        unpack2(rp[i], q0, q1);
                        a[2 * i] += q0; a[2 * i + 1] += q1;
                    }
                }
                float xs[8] = {xg0.x, xg0.y, xg0.z, xg0.w,
                               xg1.x, xg1.y, xg1.z, xg1.w};
                if (gate == 0) {
                    float zv[8];
                    #pragma unroll
                    for (int i = 0; i < 8; i++)
                        zv[i] = sigmoidf_(a[i] + xs[i]);
                    float* dz = &g_zT[colE * BATCH + bgA * 8];
                    *(float4*)dz       = make_float4(zv[0], zv[1], zv[2], zv[3]);
                    *(float4*)(dz + 4) = make_float4(zv[4], zv[5], zv[6], zv[7]);
                } else {
                    const float4* hq = (const float4*)&g_hT[colE * BATCH + bgA * 8];
                    float4 h0 = hq[0], h1 = hq[1];
                    float hv[8] = {h0.x, h0.y, h0.z, h0.w,
                                   h1.x, h1.y, h1.z, h1.w};
                    float rh[8];
                    #pragma unroll
                    for (int i = 0; i < 8; i++)
                        rh[i] = sigmoidf_(a[i] + xs[i]) * hv[i];
                    float* dr = &g_rhT[colE * BATCH + bgA * 8];
                    *(float4*)dr       = make_float4(rh[0], rh[1], rh[2], rh[3]);
                    *(float4*)(dr + 4) = make_float4(rh[4], rh[5], rh[6], rh[7]);
                }
            }
        }
        grid_barrier(gen);

        // =================== stage B: candidate + update ===================
        {
            float4 xm0, xm1, z0, z1, h0, h1;
            const int colE = blk * 8 + clB;
            if (ksB == 0) {
                const float4* xm = (const float4*)
                    &XM[((size_t)t * HID + colE) * BATCH + bgB * 8];
                xm0 = xm[0]; xm1 = xm[1];
                const float4* zq = (const float4*)&g_zT[colE * BATCH + bgB * 8];
                z0 = zq[0]; z1 = zq[1];
                const float4* hq = (const float4*)&g_hT[colE * BATCH + bgB * 8];
                h0 = hq[0]; h1 = hq[1];
            }

            ull acc0 = 0, acc1 = 0, acc2 = 0, acc3 = 0;
            float4 pf[4];
            #pragma unroll
            for (int i = 0; i < 4; i++)
                pf[i] = *(const float4*)&g_rhT[(i * NTHR + tid) * 4];

            for (int c = 0; c < 8; c++) {
                float* buf = s_h + (c & 1) * 8192;
                #pragma unroll
                for (int i = 0; i < 4; i++)
                    *(float4*)&buf[(i * NTHR + tid) * 4] = pf[i];
                __syncthreads();
                if (c < 7) {
                    #pragma unroll
                    for (int i = 0; i < 4; i++)
                        pf[i] = *(const float4*)
                            &g_rhT[(c + 1) * 8192 + (i * NTHR + tid) * 4];
                }
                const float* wp = s_wB + (c * 128 + ksB * 16) * 8 + clB;
                const float* hp = buf + ksB * 16 * 64 + bgB * 8;
                #pragma unroll 8
                for (int k = 0; k < 16; k++) {
                    float w = wp[k * 8];
                    ull w2 = pack2(w, w);
                    ulonglong2 hA = *(const ulonglong2*)(hp + k * 64);
                    ulonglong2 hB = *(const ulonglong2*)(hp + k * 64 + 4);
                    acc0 = ffma2(w2, hA.x, acc0);
                    acc1 = ffma2(w2, hA.y, acc1);
                    acc2 = ffma2(w2, hB.x, acc2);
                    acc3 = ffma2(w2, hB.y, acc3);
                }
            }

            if (ksB > 0) {
                ull* rp = s_red + ((ksB - 1) * 64 + (tid & 63)) * 4;
                rp[0] = acc0; rp[1] = acc1; rp[2] = acc2; rp[3] = acc3;
            }
            __syncthreads();
            if (ksB == 0) {
                float m8[8], q0, q1;
                unpack2(acc0, m8[0], m8[1]); unpack2(acc1, m8[2], m8[3]);
                unpack2(acc2, m8[4], m8[5]); unpack2(acc3, m8[6], m8[7]);
                #pragma unroll
                for (int j = 0; j < 7; j++) {
                    const ull* rp = s_red + (j * 64 + tid) * 4;
                    #pragma unroll
                    for (int i = 0; i < 4; i++) {
                        unpack2(rp[i], q0, q1);
                        m8[2 * i] += q0; m8[2 * i + 1] += q1;
                    }
                }
                float xs[8] = {xm0.x, xm0.y, xm0.z, xm0.w,
                               xm1.x, xm1.y, xm1.z, xm1.w};
                float zs[8] = {z0.x, z0.y, z0.z, z0.w, z1.x, z1.y, z1.z, z1.w};
                float hs[8] = {h0.x, h0.y, h0.z, h0.w, h1.x, h1.y, h1.z, h1.w};
                float hn[8];
                #pragma unroll
                for (int i = 0; i < 8; i++) {
                    float ht = tanhf(m8[i] + xs[i]);
                    hn[i] = (1.0f - zs[i]) * hs[i] + zs[i] * ht;
                }
                float* dh = &g_hT[colE * BATCH + bgB * 8];
                *(float4*)dh       = make_float4(hn[0], hn[1], hn[2], hn[3]);
                *(float4*)(dh + 4) = make_float4(hn[4], hn[5], hn[6], hn[7]);
                #pragma unroll
                for (int j = 0; j < 8; j++) {
                    int b = bgB * 8 + j;
                    out[((size_t)b * SEQ + t) * HID + colE] = hn[j];
                }
            }
        }
        grid_barrier(gen);
    }
}

// ===========================================================================
extern "C" void kernel_launch(void* const* d_in, const int* in_sizes, int n_in,
                              void* d_out, int out_size)
{
    const float* emb = (const float*)d_in[0];
    const float* ih  = (const float*)d_in[1];
    const float* Wz  = (const float*)d_in[2];
    const float* bz  = (const float*)d_in[3];
    const float* Wr  = (const float*)d_in[4];
    const float* br  = (const float*)d_in[5];
    const float* Wm  = (const float*)d_in[6];
    const float* bm  = (const float*)d_in[7];
    float* out = (float*)d_out;

    cudaFuncSetAttribute(recur_kernel,
                         cudaFuncAttributeMaxDynamicSharedMemorySize, SMEM_BYTES);

    proj_kernel<<<dim3(HID / 128, (SEQ * BATCH) / 128, 3), 256>>>(
        emb, Wz, Wr, Wm, bz, br, bm);
    init_h_kernel<<<(HID * BATCH + 255) / 256, 256>>>(ih);
    recur_kernel<<<NCTA, NTHR, SMEM_BYTES>>>(Wz, Wr, Wm, out);
}